// round 11
// baseline (speedup 1.0000x reference)
#include <cuda_runtime.h>
#include <cuda_fp16.h>
#include <math.h>

#define MAXN 100000
#define MAXE 1000000
#define F 64
#define NLAYER 4
#define ALPHA 0.1f
#define SA 68
#define BUILD_BLOCKS 148

// ---------------- device scratch (no cudaMalloc allowed) ----------------
__device__ int    g_is64;
__device__ int    g_cnt[MAXN];
__device__ int    g_ptr[MAXN + 1];
__device__ int    g_cur[MAXN];
__device__ int    g_rowv[MAXE];
__device__ int    g_colv[MAXE];
__device__ int    g_srcv[MAXE];
__device__ int    g_bsum[128];
__device__ float  g_dis[MAXN];
__device__ __half g_hA[MAXN * F];   // fp16 node features (prescaled by dis)
__device__ __half g_hB[MAXN * F];
__device__ float  g_t16[MAXN * 16];
__device__ float  g_y[MAXN];
__device__ int          g_barArrive;   // init 0; reset each use
__device__ volatile int g_barGen;      // monotonic

// ---------------- software grid barrier (all blocks resident) ----------------
__device__ __forceinline__ void grid_barrier(int nb) {
    __syncthreads();
    if (threadIdx.x == 0) {
        __threadfence();
        int gen = g_barGen;           // read BEFORE arriving
        int old = atomicAdd(&g_barArrive, 1);
        if (old == nb - 1) {
            g_barArrive = 0;
            __threadfence();
            g_barGen = gen + 1;
        } else {
            while (g_barGen == gen) { }
        }
    }
    __syncthreads();
}

// ---------------- init: detect dtype + zero counters ----------------
__global__ void k_init(const int* ei32, int n) {
    int i = blockIdx.x * blockDim.x + threadIdx.x;
    if (i < n) g_cnt[i] = 0;
    if (i == 0) {
        int odd_or = 0;
        for (int k = 1; k < 256; k += 2) odd_or |= ei32[k];
        g_is64 = (odd_or == 0) ? 1 : 0;
    }
}

// convert edges to int32 + in-degree histogram on col
__global__ void k_convert_count(const void* ei, int E) {
    int e = blockIdx.x * blockDim.x + threadIdx.x;
    if (e >= E) return;
    int r, c;
    if (g_is64) {
        const long long* p = (const long long*)ei;
        r = (int)p[e];
        c = (int)p[e + E];
    } else {
        const int* p = (const int*)ei;
        r = p[e];
        c = p[e + E];
    }
    g_rowv[e] = r;
    g_colv[e] = c;
    atomicAdd(&g_cnt[c], 1);
}

// ====== fused build: scan (dis, ptr, cur) + scatter + x prescale ============
// 148 blocks x 1024 threads, all resident -> software grid barriers are safe.
__global__ void __launch_bounds__(1024) k_build(const float* __restrict__ x,
                                                int E, int n) {
    __shared__ int s[1024];
    __shared__ int base_sh;
    int tid = threadIdx.x;
    int bid = blockIdx.x;
    int nchunks = (n + 1023) / 1024;

    // phase 1: per-chunk scan + dis
    if (bid < nchunks) {
        int i = bid * 1024 + tid;
        int v = (i < n) ? g_cnt[i] : 0;
        if (i < n) g_dis[i] = rsqrtf((float)v + 1.0f);  // +1 self loop
        s[tid] = v;
        __syncthreads();
        for (int off = 1; off < 1024; off <<= 1) {
            int t = (tid >= off) ? s[tid - off] : 0;
            __syncthreads();
            s[tid] += t;
            __syncthreads();
        }
        if (i < n) g_ptr[i] = s[tid] - v;  // exclusive within chunk
        if (tid == 1023) g_bsum[bid] = s[1023];
    }
    grid_barrier(BUILD_BLOCKS);

    // phase 2: add chunk base, init cur
    if (bid < nchunks) {
        if (tid == 0) {
            int r = 0;
            for (int b = 0; b < bid; b++) r += g_bsum[b];
            base_sh = r;
        }
        __syncthreads();
        int i = bid * 1024 + tid;
        if (i < n) {
            int p = g_ptr[i] + base_sh;
            g_ptr[i] = p;
            g_cur[i] = p;
        }
        if (i == 0) g_ptr[n] = E;
    }
    grid_barrier(BUILD_BLOCKS);

    // phase 3: scatter edges + prescale x by dis into g_hA (fp16)
    int total = E + n * 16;
    int stride = BUILD_BLOCKS * 1024;
    for (int i = bid * 1024 + tid; i < total; i += stride) {
        if (i < E) {
            int c = g_colv[i];
            int pos = atomicAdd(&g_cur[c], 1);
            g_srcv[pos] = g_rowv[i];
        } else {
            int j = i - E;  // float4 index
            int node = j >> 4;
            float4 v = ((const float4*)x)[j];
            float d = g_dis[node];
            __half2 h0 = __floats2half2_rn(v.x * d, v.y * d);
            __half2 h1 = __floats2half2_rn(v.z * d, v.w * d);
            ((__half2*)g_hA)[j * 2 + 0] = h0;
            ((__half2*)g_hA)[j * 2 + 1] = h1;
        }
    }
}

// ============ fused layer: propagate + mix + GEMM64x64 + relu + prescale ====
// warp handles 4 nodes; srcv fetched coalesced (lane-parallel) + shuffled.
__device__ __forceinline__ void gather_tile(const __half2* __restrict__ H,
                                            const float2* __restrict__ X,
                                            float* As, int r0, int n,
                                            int wid, int lane) {
#pragma unroll 1
    for (int i = 0; i < 4; i++) {
        int rr = wid * 4 + i;
        int node = r0 + rr;
        float2 o = make_float2(0.f, 0.f);
        if (node < n) {
            int beg = g_ptr[node], end = g_ptr[node + 1];
            float d = g_dis[node];
            float2 hself = __half22float2(H[node * 32 + lane]);  // issue early
            float2 xv = X[node * 32 + lane];
            float sx = 0.f, sy = 0.f;
            for (int pos = beg; pos < end; pos += 32) {
                int cnt = min(32, end - pos);
                int sv = (lane < cnt) ? g_srcv[pos + lane] : 0;
                int j = 0;
                for (; j + 4 <= cnt; j += 4) {
                    int s0 = __shfl_sync(0xffffffffu, sv, j);
                    int s1 = __shfl_sync(0xffffffffu, sv, j + 1);
                    int s2 = __shfl_sync(0xffffffffu, sv, j + 2);
                    int s3 = __shfl_sync(0xffffffffu, sv, j + 3);
                    float2 v0 = __half22float2(H[s0 * 32 + lane]);
                    float2 v1 = __half22float2(H[s1 * 32 + lane]);
                    float2 v2 = __half22float2(H[s2 * 32 + lane]);
                    float2 v3 = __half22float2(H[s3 * 32 + lane]);
                    sx += v0.x + v1.x + v2.x + v3.x;
                    sy += v0.y + v1.y + v2.y + v3.y;
                }
                for (; j < cnt; j++) {
                    int sj = __shfl_sync(0xffffffffu, sv, j);
                    float2 v = __half22float2(H[sj * 32 + lane]);
                    sx += v.x; sy += v.y;
                }
            }
            o.x = (1.0f - ALPHA) * d * (sx + hself.x) + ALPHA * xv.x;
            o.y = (1.0f - ALPHA) * d * (sy + hself.y) + ALPHA * xv.y;
        }
        *(float2*)&As[rr * SA + lane * 2] = o;
    }
}

__global__ void __launch_bounds__(512) k_layer(
    const __half2* __restrict__ hs, const float* __restrict__ x0,
    const float* __restrict__ W, __half* __restrict__ Out, int n) {
    __shared__ float Ws[64 * SA];
    __shared__ float As[64 * SA];
    int tid = threadIdx.x;
    int r0 = blockIdx.x * 64;
    const float4* W4 = (const float4*)W;
    for (int i = tid; i < 1024; i += 512) {
        int k = i >> 4, q = i & 15;
        *(float4*)&Ws[k * SA + q * 4] = W4[i];
    }
    gather_tile(hs, (const float2*)x0, As, r0, n, tid >> 5, tid & 31);
    __syncthreads();

    int tx = tid & 15, ty = tid >> 4;  // ty 0..31, 2 rows each
    float acc[2][4] = {};
#pragma unroll 8
    for (int k = 0; k < 64; k++) {
        float4 w4 = *(const float4*)&Ws[k * SA + tx * 4];
        float a0 = As[(ty * 2 + 0) * SA + k];
        float a1 = As[(ty * 2 + 1) * SA + k];
        acc[0][0] += a0 * w4.x; acc[0][1] += a0 * w4.y; acc[0][2] += a0 * w4.z; acc[0][3] += a0 * w4.w;
        acc[1][0] += a1 * w4.x; acc[1][1] += a1 * w4.y; acc[1][2] += a1 * w4.z; acc[1][3] += a1 * w4.w;
    }
#pragma unroll
    for (int i = 0; i < 2; i++) {
        int r = r0 + ty * 2 + i;
        if (r < n) {
            float sc = g_dis[r];
            __half2 h0 = __floats2half2_rn(fmaxf(acc[i][0], 0.f) * sc,
                                           fmaxf(acc[i][1], 0.f) * sc);
            __half2 h1 = __floats2half2_rn(fmaxf(acc[i][2], 0.f) * sc,
                                           fmaxf(acc[i][3], 0.f) * sc);
            uint2 pk;
            pk.x = *reinterpret_cast<unsigned int*>(&h0);
            pk.y = *reinterpret_cast<unsigned int*>(&h1);
            *(uint2*)((__half2*)Out + r * 32 + tx * 2) = pk;
        }
    }
}

// ===== last layer: propagate + mix + GEMM64x64 + relu + GEMM64x16*dis ========
__global__ void __launch_bounds__(512) k_layer_last(
    const __half2* __restrict__ hs, const float* __restrict__ x0,
    const float* __restrict__ W, const float* __restrict__ W1,
    float* __restrict__ T16, int n) {
    __shared__ float Ws[64 * SA];
    __shared__ float As[64 * SA];
    __shared__ float W1s[64 * 16];
    int tid = threadIdx.x;
    int r0 = blockIdx.x * 64;
    const float4* W4 = (const float4*)W;
    for (int i = tid; i < 1024; i += 512) {
        int k = i >> 4, q = i & 15;
        *(float4*)&Ws[k * SA + q * 4] = W4[i];
    }
    for (int i = tid; i < 1024; i += 512) W1s[i] = W1[i];
    gather_tile(hs, (const float2*)x0, As, r0, n, tid >> 5, tid & 31);
    __syncthreads();

    int tx = tid & 15, ty = tid >> 4;
    float acc[2][4] = {};
#pragma unroll 8
    for (int k = 0; k < 64; k++) {
        float4 w4 = *(const float4*)&Ws[k * SA + tx * 4];
        float a0 = As[(ty * 2 + 0) * SA + k];
        float a1 = As[(ty * 2 + 1) * SA + k];
        acc[0][0] += a0 * w4.x; acc[0][1] += a0 * w4.y; acc[0][2] += a0 * w4.z; acc[0][3] += a0 * w4.w;
        acc[1][0] += a1 * w4.x; acc[1][1] += a1 * w4.y; acc[1][2] += a1 * w4.z; acc[1][3] += a1 * w4.w;
    }
    __syncthreads();  // reuse Ws region for relu(h)
#pragma unroll
    for (int i = 0; i < 2; i++) {
        int rr = ty * 2 + i;
        Ws[rr * SA + tx * 4 + 0] = fmaxf(acc[i][0], 0.f);
        Ws[rr * SA + tx * 4 + 1] = fmaxf(acc[i][1], 0.f);
        Ws[rr * SA + tx * 4 + 2] = fmaxf(acc[i][2], 0.f);
        Ws[rr * SA + tx * 4 + 3] = fmaxf(acc[i][3], 0.f);
    }
    __syncthreads();
    // h(64x64 in Ws) @ W1(64x16) -> T16, prescaled by dis
    for (int idx = tid; idx < 1024; idx += 512) {
        int rr = idx >> 4, j = idx & 15;
        int r = r0 + rr;
        if (r < n) {
            float a = 0.f;
#pragma unroll 8
            for (int k = 0; k < 64; k++) a += Ws[rr * SA + k] * W1s[k * 16 + j];
            T16[r * 16 + j] = a * g_dis[r];
        }
    }
}

// ---------------- propagate 16-wide + b1, fused 16->1 GEMV, prescale ----------
__global__ void k_prop16_gemv(const float* __restrict__ ts, const float* __restrict__ b1,
                              const float* __restrict__ w2, float* __restrict__ ys, int n) {
    int t = threadIdx.x;
    int node = blockIdx.x * 16 + (t >> 4);
    int f = t & 15;
    bool ok = node < n;
    int beg = 0, end = 0;
    if (ok) { beg = g_ptr[node]; end = g_ptr[node + 1]; }
    float s = 0.f;
    int e = beg;
    for (; e + 4 <= end; e += 4) {
        int s0 = g_srcv[e], s1 = g_srcv[e + 1], s2 = g_srcv[e + 2], s3 = g_srcv[e + 3];
        s += ts[s0 * 16 + f] + ts[s1 * 16 + f] + ts[s2 * 16 + f] + ts[s3 * 16 + f];
    }
    for (; e < end; e++) s += ts[g_srcv[e] * 16 + f];
    float d = ok ? g_dis[node] : 0.f;
    float self = ok ? ts[node * 16 + f] : 0.f;
    float val = d * (s + self) + b1[f];
    float prod = val * w2[f];
    prod += __shfl_xor_sync(0xffffffffu, prod, 8);
    prod += __shfl_xor_sync(0xffffffffu, prod, 4);
    prod += __shfl_xor_sync(0xffffffffu, prod, 2);
    prod += __shfl_xor_sync(0xffffffffu, prod, 1);
    if (ok && f == 0) ys[node] = d * prod;
}

// ---------------- scalar propagate + b2 + sigmoid ----------------
__global__ void k_prop1_sig(const float* __restrict__ ys, const float* __restrict__ b2,
                            float* __restrict__ out, int n) {
    int node = blockIdx.x * blockDim.x + threadIdx.x;
    if (node >= n) return;
    int beg = g_ptr[node], end = g_ptr[node + 1];
    float s = 0.f;
    int e = beg;
    for (; e + 4 <= end; e += 4) {
        int s0 = g_srcv[e], s1 = g_srcv[e + 1], s2 = g_srcv[e + 2], s3 = g_srcv[e + 3];
        s += ys[s0] + ys[s1] + ys[s2] + ys[s3];
    }
    for (; e < end; e++) s += ys[g_srcv[e]];
    float d = g_dis[node];
    float v = d * (s + ys[node]) + b2[0];
    out[node] = 1.0f / (1.0f + expf(-v));
}

// ---------------- launch ----------------
extern "C" void kernel_launch(void* const* d_in, const int* in_sizes, int n_in,
                              void* d_out, int out_size) {
    const float* x  = (const float*)d_in[0];
    const void*  ei = d_in[1];
    const float* gw = (const float*)d_in[2];  // (4,64,64)
    const float* w1 = (const float*)d_in[3];  // (64,16)
    const float* b1 = (const float*)d_in[4];
    const float* w2 = (const float*)d_in[5];  // (16,1)
    const float* b2 = (const float*)d_in[6];
    float* out = (float*)d_out;

    const int N = in_sizes[0] / F;
    const int E = in_sizes[1] / 2;

    __half* hA; cudaGetSymbolAddress((void**)&hA, g_hA);
    __half* hB; cudaGetSymbolAddress((void**)&hB, g_hB);
    float* t16; cudaGetSymbolAddress((void**)&t16, g_t16);
    float* yv;  cudaGetSymbolAddress((void**)&yv,  g_y);

    const int T = 256;
    int nb_n = (N + T - 1) / T;
    int nb_e = (E + T - 1) / T;
    int nb_g = (N + 63) / 64;
    int nb_g16 = (N + 15) / 16;

    // 0..2: graph norm + CSR build (+ fp16 x prescale into hA)
    k_init<<<nb_n, T>>>((const int*)ei, N);
    k_convert_count<<<nb_e, T>>>(ei, E);
    k_build<<<BUILD_BLOCKS, 1024>>>(x, E, N);

    // 3..6: GCN2Conv stack, fused per layer, fp16 inter-layer features
    k_layer<<<nb_g, 512>>>((const __half2*)hA, x, gw + 0 * 4096, hB, N);
    k_layer<<<nb_g, 512>>>((const __half2*)hB, x, gw + 1 * 4096, hA, N);
    k_layer<<<nb_g, 512>>>((const __half2*)hA, x, gw + 2 * 4096, hB, N);
    k_layer_last<<<nb_g, 512>>>((const __half2*)hB, x, gw + 3 * 4096, w1, t16, N);

    // tail
    k_prop16_gemv<<<nb_g16, 256>>>(t16, b1, w2, yv, N);
    k_prop1_sig<<<nb_n, T>>>(yv, b2, out, N);
}

// round 12
// speedup vs baseline: 1.2340x; 1.2340x over previous
#include <cuda_runtime.h>
#include <cuda_fp16.h>
#include <mma.h>
#include <math.h>

using namespace nvcuda;

#define MAXN 100000
#define MAXE 1000000
#define F 64
#define ALPHA 0.1f
#define BUILD_BLOCKS 148
#define LDA 72   // halves, As16/Ws16 leading dim (144B rows, 16B-aligned)
#define LDC 68   // floats, Cs leading dim (272B rows, 16B-aligned)
#define SMEM_BYTES (2 * 64 * LDA * 2)   // 18432: As16 + Ws16; Cs (17408) overlays

// ---------------- device scratch (no cudaMalloc allowed) ----------------
__device__ int    g_is64;
__device__ int    g_cnt[MAXN];
__device__ int    g_ptr[MAXN + 1];
__device__ int    g_cur[MAXN];
__device__ int    g_rowv[MAXE];
__device__ int    g_colv[MAXE];
__device__ int    g_srcv[MAXE];
__device__ int    g_bsum[128];
__device__ float  g_dis[MAXN];
__device__ __half g_hA[MAXN * F];   // fp16 node features (prescaled by dis)
__device__ __half g_hB[MAXN * F];
__device__ float  g_t16[MAXN * 16];
__device__ float  g_y[MAXN];
__device__ int          g_barArrive;
__device__ volatile int g_barGen;

// ---------------- software grid barrier (all blocks resident) ----------------
__device__ __forceinline__ void grid_barrier(int nb) {
    __syncthreads();
    if (threadIdx.x == 0) {
        __threadfence();
        int gen = g_barGen;
        int old = atomicAdd(&g_barArrive, 1);
        if (old == nb - 1) {
            g_barArrive = 0;
            __threadfence();
            g_barGen = gen + 1;
        } else {
            while (g_barGen == gen) { }
        }
    }
    __syncthreads();
}

// ---------------- init: detect dtype + zero counters ----------------
__global__ void k_init(const int* ei32, int n) {
    int i = blockIdx.x * blockDim.x + threadIdx.x;
    if (i < n) g_cnt[i] = 0;
    if (i == 0) {
        int odd_or = 0;
        for (int k = 1; k < 256; k += 2) odd_or |= ei32[k];
        g_is64 = (odd_or == 0) ? 1 : 0;
    }
}

// convert edges to int32 + in-degree histogram on col
__global__ void k_convert_count(const void* ei, int E) {
    int e = blockIdx.x * blockDim.x + threadIdx.x;
    if (e >= E) return;
    int r, c;
    if (g_is64) {
        const long long* p = (const long long*)ei;
        r = (int)p[e];
        c = (int)p[e + E];
    } else {
        const int* p = (const int*)ei;
        r = p[e];
        c = p[e + E];
    }
    g_rowv[e] = r;
    g_colv[e] = c;
    atomicAdd(&g_cnt[c], 1);
}

// ====== fused build: scan (dis, ptr, cur) + scatter + x prescale ============
__global__ void __launch_bounds__(1024) k_build(const float* __restrict__ x,
                                                int E, int n) {
    __shared__ int s[1024];
    __shared__ int base_sh;
    int tid = threadIdx.x;
    int bid = blockIdx.x;
    int nchunks = (n + 1023) / 1024;

    if (bid < nchunks) {
        int i = bid * 1024 + tid;
        int v = (i < n) ? g_cnt[i] : 0;
        if (i < n) g_dis[i] = rsqrtf((float)v + 1.0f);  // +1 self loop
        s[tid] = v;
        __syncthreads();
        for (int off = 1; off < 1024; off <<= 1) {
            int t = (tid >= off) ? s[tid - off] : 0;
            __syncthreads();
            s[tid] += t;
            __syncthreads();
        }
        if (i < n) g_ptr[i] = s[tid] - v;
        if (tid == 1023) g_bsum[bid] = s[1023];
    }
    grid_barrier(BUILD_BLOCKS);

    if (bid < nchunks) {
        if (tid == 0) {
            int r = 0;
            for (int b = 0; b < bid; b++) r += g_bsum[b];
            base_sh = r;
        }
        __syncthreads();
        int i = bid * 1024 + tid;
        if (i < n) {
            int p = g_ptr[i] + base_sh;
            g_ptr[i] = p;
            g_cur[i] = p;
        }
        if (i == 0) g_ptr[n] = E;
    }
    grid_barrier(BUILD_BLOCKS);

    int total = E + n * 16;
    int stride = BUILD_BLOCKS * 1024;
    for (int i = bid * 1024 + tid; i < total; i += stride) {
        if (i < E) {
            int c = g_colv[i];
            int pos = atomicAdd(&g_cur[c], 1);
            g_srcv[pos] = g_rowv[i];
        } else {
            int j = i - E;
            int node = j >> 4;
            float4 v = ((const float4*)x)[j];
            float d = g_dis[node];
            __half2 h0 = __floats2half2_rn(v.x * d, v.y * d);
            __half2 h1 = __floats2half2_rn(v.z * d, v.w * d);
            ((__half2*)g_hA)[j * 2 + 0] = h0;
            ((__half2*)g_hA)[j * 2 + 1] = h1;
        }
    }
}

// ---------------- gather: warp = 4 groups x 8 lanes, LDG.128 per 4 edges ----
#define HSHF(a, m) do { int _t = __shfl_xor_sync(0xffffffffu, *(int*)&(a), (m)); \
                        (a) = __hadd2((a), *(__half2*)&_t); } while (0)

__device__ __forceinline__ void gather_tile(const uint4* __restrict__ H4,
                                            const float4* __restrict__ X4,
                                            __half* As16, int r0, int n,
                                            int wid, int lane) {
    int group = lane >> 3;   // 0..3: which edge of the quad
    int gl = lane & 7;       // 16B slice of the 128B row
#pragma unroll 1
    for (int i = 0; i < 8; i++) {
        int rr = wid * 8 + i;
        int node = r0 + rr;
        __half2 a0 = __floats2half2_rn(0.f, 0.f), a1 = a0, a2 = a0, a3 = a0;
        int beg = 0, end = 0;
        if (node < n) { beg = g_ptr[node]; end = g_ptr[node + 1]; }
        for (int pos = beg; pos < end; pos += 32) {
            int cnt = min(32, end - pos);
            int sv = (lane < cnt) ? g_srcv[pos + lane] : 0;
#pragma unroll 1
            for (int j = 0; j < cnt; j += 4) {
                int src = __shfl_sync(0xffffffffu, sv, j + group);
                if (j + group < cnt) {
                    uint4 v = H4[src * 8 + gl];
                    a0 = __hadd2(a0, *(__half2*)&v.x);
                    a1 = __hadd2(a1, *(__half2*)&v.y);
                    a2 = __hadd2(a2, *(__half2*)&v.z);
                    a3 = __hadd2(a3, *(__half2*)&v.w);
                }
            }
        }
        // cross-group reduce (lanes {l, l+8, l+16, l+24} hold same slice)
        HSHF(a0, 8);  HSHF(a1, 8);  HSHF(a2, 8);  HSHF(a3, 8);
        HSHF(a0, 16); HSHF(a1, 16); HSHF(a2, 16); HSHF(a3, 16);
        if (lane < 8) {
            float2 s0 = __half22float2(a0), s1 = __half22float2(a1);
            float2 s2 = __half22float2(a2), s3 = __half22float2(a3);
            float d = 0.f;
            float2 h0 = make_float2(0.f, 0.f), h1 = h0, h2 = h0, h3 = h0;
            float4 xa = make_float4(0.f, 0.f, 0.f, 0.f), xb = xa;
            if (node < n) {
                d = g_dis[node];
                uint4 hv = H4[node * 8 + gl];
                h0 = __half22float2(*(__half2*)&hv.x);
                h1 = __half22float2(*(__half2*)&hv.y);
                h2 = __half22float2(*(__half2*)&hv.z);
                h3 = __half22float2(*(__half2*)&hv.w);
                xa = X4[node * 16 + gl * 2];
                xb = X4[node * 16 + gl * 2 + 1];
            }
            const float A9 = 1.0f - ALPHA, A1 = ALPHA;
            __half2 o0 = __floats2half2_rn(A9 * d * (s0.x + h0.x) + A1 * xa.x,
                                           A9 * d * (s0.y + h0.y) + A1 * xa.y);
            __half2 o1 = __floats2half2_rn(A9 * d * (s1.x + h1.x) + A1 * xa.z,
                                           A9 * d * (s1.y + h1.y) + A1 * xa.w);
            __half2 o2 = __floats2half2_rn(A9 * d * (s2.x + h2.x) + A1 * xb.x,
                                           A9 * d * (s2.y + h2.y) + A1 * xb.y);
            __half2 o3 = __floats2half2_rn(A9 * d * (s3.x + h3.x) + A1 * xb.z,
                                           A9 * d * (s3.y + h3.y) + A1 * xb.w);
            uint4 pk;
            pk.x = *(unsigned int*)&o0; pk.y = *(unsigned int*)&o1;
            pk.z = *(unsigned int*)&o2; pk.w = *(unsigned int*)&o3;
            *((uint4*)(As16 + rr * LDA) + gl) = pk;
        }
    }
}

// ---------------- shared wmma GEMM: Cs(64x64 fp32) = As16 @ Ws16 ------------
__device__ __forceinline__ void wmma_gemm(const __half* As16, const __half* Ws16,
                                          float* Cs, int wid) {
    int tm = wid >> 1;               // 0..3
    int tn0 = (wid & 1) * 2;         // 0 or 2
    wmma::fragment<wmma::accumulator, 16, 16, 16, float> c0, c1;
    wmma::fill_fragment(c0, 0.f);
    wmma::fill_fragment(c1, 0.f);
#pragma unroll
    for (int k = 0; k < 4; k++) {
        wmma::fragment<wmma::matrix_a, 16, 16, 16, __half, wmma::row_major> a;
        wmma::fragment<wmma::matrix_b, 16, 16, 16, __half, wmma::row_major> b0, b1;
        wmma::load_matrix_sync(a, As16 + tm * 16 * LDA + k * 16, LDA);
        wmma::load_matrix_sync(b0, Ws16 + k * 16 * LDA + tn0 * 16, LDA);
        wmma::load_matrix_sync(b1, Ws16 + k * 16 * LDA + (tn0 + 1) * 16, LDA);
        wmma::mma_sync(c0, a, b0, c0);
        wmma::mma_sync(c1, a, b1, c1);
    }
    __syncthreads();  // everyone done reading As16/Ws16; Cs overlays them
    wmma::store_matrix_sync(Cs + tm * 16 * LDC + tn0 * 16, c0, LDC, wmma::mem_row_major);
    wmma::store_matrix_sync(Cs + tm * 16 * LDC + (tn0 + 1) * 16, c1, LDC, wmma::mem_row_major);
}

// ============ fused layer: gather + mix -> HMMA -> relu*dis -> fp16 out =====
__global__ void __launch_bounds__(256) k_layer(
    const __half* __restrict__ hs, const float* __restrict__ x0,
    const float* __restrict__ W, __half* __restrict__ Out, int n) {
    __shared__ __align__(16) unsigned char smem_raw[SMEM_BYTES];
    __half* As16 = (__half*)smem_raw;                    // [64][LDA]
    __half* Wp   = (__half*)(smem_raw + 64 * LDA * 2);   // [64][LDA]
    float*  Cs   = (float*)smem_raw;                     // overlay [64][LDC]
    int tid = threadIdx.x;
    int r0 = blockIdx.x * 64;

    for (int i = tid; i < 4096; i += 256) {
        int k = i >> 6, j = i & 63;
        Wp[k * LDA + j] = __float2half(W[i]);
    }
    gather_tile((const uint4*)hs, (const float4*)x0, As16, r0, n, tid >> 5, tid & 31);
    __syncthreads();

    wmma_gemm(As16, Wp, Cs, tid >> 5);
    __syncthreads();

    // epilogue: relu * dis -> fp16
    int rr = tid >> 2, cb = tid & 3;
    int r = r0 + rr;
    if (r < n) {
        float sc = g_dis[r];
        const float* row = Cs + rr * LDC + cb * 16;
        __half2 h[8];
#pragma unroll
        for (int q = 0; q < 8; q++) {
            float v0 = fmaxf(row[q * 2 + 0], 0.f) * sc;
            float v1 = fmaxf(row[q * 2 + 1], 0.f) * sc;
            h[q] = __floats2half2_rn(v0, v1);
        }
        uint4* dst = (uint4*)(Out + r * 64) + cb * 2;
        uint4 p0, p1;
        p0.x = *(unsigned int*)&h[0]; p0.y = *(unsigned int*)&h[1];
        p0.z = *(unsigned int*)&h[2]; p0.w = *(unsigned int*)&h[3];
        p1.x = *(unsigned int*)&h[4]; p1.y = *(unsigned int*)&h[5];
        p1.z = *(unsigned int*)&h[6]; p1.w = *(unsigned int*)&h[7];
        dst[0] = p0;
        dst[1] = p1;
    }
}

// ===== last layer: gather+mix -> HMMA -> relu -> GEMM64x16 * dis -> T16 =====
__global__ void __launch_bounds__(256) k_layer_last(
    const __half* __restrict__ hs, const float* __restrict__ x0,
    const float* __restrict__ W, const float* __restrict__ W1,
    float* __restrict__ T16, int n) {
    __shared__ __align__(16) unsigned char smem_raw[SMEM_BYTES];
    __shared__ float W1s[64 * 16];
    __half* As16 = (__half*)smem_raw;
    __half* Wp   = (__half*)(smem_raw + 64 * LDA * 2);
    float*  Cs   = (float*)smem_raw;
    int tid = threadIdx.x;
    int r0 = blockIdx.x * 64;

    for (int i = tid; i < 4096; i += 256) {
        int k = i >> 6, j = i & 63;
        Wp[k * LDA + j] = __float2half(W[i]);
    }
    for (int i = tid; i < 1024; i += 256) W1s[i] = W1[i];
    gather_tile((const uint4*)hs, (const float4*)x0, As16, r0, n, tid >> 5, tid & 31);
    __syncthreads();

    wmma_gemm(As16, Wp, Cs, tid >> 5);
    __syncthreads();

    // relu in place
    for (int i = tid; i < 4096; i += 256) {
        int rr = i >> 6, k = i & 63;
        Cs[rr * LDC + k] = fmaxf(Cs[rr * LDC + k], 0.f);
    }
    __syncthreads();

    // h(64x64 Cs) @ W1(64x16) -> T16, prescaled by dis
    for (int idx = tid; idx < 1024; idx += 256) {
        int rr = idx >> 4, j = idx & 15;
        int r = r0 + rr;
        if (r < n) {
            float a = 0.f;
#pragma unroll 8
            for (int k = 0; k < 64; k++) a += Cs[rr * LDC + k] * W1s[k * 16 + j];
            T16[r * 16 + j] = a * g_dis[r];
        }
    }
}

// ---------------- propagate 16-wide + b1, fused 16->1 GEMV, prescale ----------
__global__ void k_prop16_gemv(const float* __restrict__ ts, const float* __restrict__ b1,
                              const float* __restrict__ w2, float* __restrict__ ys, int n) {
    int t = threadIdx.x;
    int node = blockIdx.x * 16 + (t >> 4);
    int f = t & 15;
    bool ok = node < n;
    int beg = 0, end = 0;
    if (ok) { beg = g_ptr[node]; end = g_ptr[node + 1]; }
    float s = 0.f;
    int e = beg;
    for (; e + 4 <= end; e += 4) {
        int s0 = g_srcv[e], s1 = g_srcv[e + 1], s2 = g_srcv[e + 2], s3 = g_srcv[e + 3];
        s += ts[s0 * 16 + f] + ts[s1 * 16 + f] + ts[s2 * 16 + f] + ts[s3 * 16 + f];
    }
    for (; e < end; e++) s += ts[g_srcv[e] * 16 + f];
    float d = ok ? g_dis[node] : 0.f;
    float self = ok ? ts[node * 16 + f] : 0.f;
    float val = d * (s + self) + b1[f];
    float prod = val * w2[f];
    prod += __shfl_xor_sync(0xffffffffu, prod, 8);
    prod += __shfl_xor_sync(0xffffffffu, prod, 4);
    prod += __shfl_xor_sync(0xffffffffu, prod, 2);
    prod += __shfl_xor_sync(0xffffffffu, prod, 1);
    if (ok && f == 0) ys[node] = d * prod;
}

// ---------------- scalar propagate + b2 + sigmoid ----------------
__global__ void k_prop1_sig(const float* __restrict__ ys, const float* __restrict__ b2,
                            float* __restrict__ out, int n) {
    int node = blockIdx.x * blockDim.x + threadIdx.x;
    if (node >= n) return;
    int beg = g_ptr[node], end = g_ptr[node + 1];
    float s = 0.f;
    int e = beg;
    for (; e + 4 <= end; e += 4) {
        int s0 = g_srcv[e], s1 = g_srcv[e + 1], s2 = g_srcv[e + 2], s3 = g_srcv[e + 3];
        s += ys[s0] + ys[s1] + ys[s2] + ys[s3];
    }
    for (; e < end; e++) s += ys[g_srcv[e]];
    float d = g_dis[node];
    float v = d * (s + ys[node]) + b2[0];
    out[node] = 1.0f / (1.0f + expf(-v));
}

// ---------------- launch ----------------
extern "C" void kernel_launch(void* const* d_in, const int* in_sizes, int n_in,
                              void* d_out, int out_size) {
    const float* x  = (const float*)d_in[0];
    const void*  ei = d_in[1];
    const float* gw = (const float*)d_in[2];  // (4,64,64)
    const float* w1 = (const float*)d_in[3];  // (64,16)
    const float* b1 = (const float*)d_in[4];
    const float* w2 = (const float*)d_in[5];  // (16,1)
    const float* b2 = (const float*)d_in[6];
    float* out = (float*)d_out;

    const int N = in_sizes[0] / F;
    const int E = in_sizes[1] / 2;

    __half* hA; cudaGetSymbolAddress((void**)&hA, g_hA);
    __half* hB; cudaGetSymbolAddress((void**)&hB, g_hB);
    float* t16; cudaGetSymbolAddress((void**)&t16, g_t16);
    float* yv;  cudaGetSymbolAddress((void**)&yv,  g_y);

    const int T = 256;
    int nb_n = (N + T - 1) / T;
    int nb_e = (E + T - 1) / T;
    int nb_g = (N + 63) / 64;
    int nb_g16 = (N + 15) / 16;

    // 0..2: graph norm + CSR build (+ fp16 x prescale into hA)
    k_init<<<nb_n, T>>>((const int*)ei, N);
    k_convert_count<<<nb_e, T>>>(ei, E);
    k_build<<<BUILD_BLOCKS, 1024>>>(x, E, N);

    // 3..6: GCN2Conv stack: fused gather + HMMA per layer
    k_layer<<<nb_g, 256>>>(hA, x, gw + 0 * 4096, hB, N);
    k_layer<<<nb_g, 256>>>(hB, x, gw + 1 * 4096, hA, N);
    k_layer<<<nb_g, 256>>>(hA, x, gw + 2 * 4096, hB, N);
    k_layer_last<<<nb_g, 256>>>(hB, x, gw + 3 * 4096, w1, t16, N);

    // tail
    k_prop16_gemv<<<nb_g16, 256>>>(t16, b1, w2, yv, N);
    k_prop1_sig<<<nb_n, T>>>(yv, b2, out, N);
}

// round 13
// speedup vs baseline: 1.2414x; 1.0061x over previous
#include <cuda_runtime.h>
#include <cuda_fp16.h>
#include <mma.h>
#include <math.h>

using namespace nvcuda;

#define MAXN 100000
#define MAXE 1000000
#define F 64
#define ALPHA 0.1f
#define BUILD_BLOCKS 148
#define LDA 72   // halves, As16/Ws16 leading dim (144B rows, 16B-aligned)
#define LDC 68   // floats, Cs leading dim (272B rows, 16B-aligned)
#define SMEM_BYTES (2 * 64 * LDA * 2)   // 18432: As16 + Ws16; Cs (17408) overlays

// ---------------- device scratch (no cudaMalloc allowed) ----------------
__device__ int    g_is64;
__device__ int    g_cnt[MAXN];
__device__ int    g_ptr[MAXN + 1];
__device__ int    g_cur[MAXN];
__device__ int    g_rowv[MAXE];
__device__ int    g_colv[MAXE];
__device__ int    g_srcv[MAXE];
__device__ int    g_bsum[128];
__device__ float  g_dis[MAXN];
__device__ __half g_hA[MAXN * F];   // fp16 node features (prescaled by dis)
__device__ __half g_hB[MAXN * F];
__device__ __half g_xa[MAXN * F];   // fp16 alpha * x
__device__ float  g_t16[MAXN * 16];
__device__ float  g_y[MAXN];
__device__ int          g_barArrive;
__device__ volatile int g_barGen;

// ---------------- software grid barrier (all blocks resident) ----------------
__device__ __forceinline__ void grid_barrier(int nb) {
    __syncthreads();
    if (threadIdx.x == 0) {
        __threadfence();
        int gen = g_barGen;
        int old = atomicAdd(&g_barArrive, 1);
        if (old == nb - 1) {
            g_barArrive = 0;
            __threadfence();
            g_barGen = gen + 1;
        } else {
            while (g_barGen == gen) { }
        }
    }
    __syncthreads();
}

// ---------------- init: detect dtype + zero counters ----------------
__global__ void k_init(const int* ei32, int n) {
    int i = blockIdx.x * blockDim.x + threadIdx.x;
    if (i < n) g_cnt[i] = 0;
    if (i == 0) {
        int odd_or = 0;
        for (int k = 1; k < 256; k += 2) odd_or |= ei32[k];
        g_is64 = (odd_or == 0) ? 1 : 0;
    }
}

// convert edges to int32 + in-degree histogram on col
__global__ void k_convert_count(const void* ei, int E) {
    int e = blockIdx.x * blockDim.x + threadIdx.x;
    if (e >= E) return;
    int r, c;
    if (g_is64) {
        const long long* p = (const long long*)ei;
        r = (int)p[e];
        c = (int)p[e + E];
    } else {
        const int* p = (const int*)ei;
        r = p[e];
        c = p[e + E];
    }
    g_rowv[e] = r;
    g_colv[e] = c;
    atomicAdd(&g_cnt[c], 1);
}

// ====== fused build: scan (dis, ptr, cur) + scatter + x prescale ============
__global__ void __launch_bounds__(1024) k_build(const float* __restrict__ x,
                                                int E, int n) {
    __shared__ int s[1024];
    __shared__ int base_sh;
    int tid = threadIdx.x;
    int bid = blockIdx.x;
    int nchunks = (n + 1023) / 1024;

    if (bid < nchunks) {
        int i = bid * 1024 + tid;
        int v = (i < n) ? g_cnt[i] : 0;
        if (i < n) g_dis[i] = rsqrtf((float)v + 1.0f);  // +1 self loop
        s[tid] = v;
        __syncthreads();
        for (int off = 1; off < 1024; off <<= 1) {
            int t = (tid >= off) ? s[tid - off] : 0;
            __syncthreads();
            s[tid] += t;
            __syncthreads();
        }
        if (i < n) g_ptr[i] = s[tid] - v;
        if (tid == 1023) g_bsum[bid] = s[1023];
    }
    grid_barrier(BUILD_BLOCKS);

    if (bid < nchunks) {
        if (tid == 0) {
            int r = 0;
            for (int b = 0; b < bid; b++) r += g_bsum[b];
            base_sh = r;
        }
        __syncthreads();
        int i = bid * 1024 + tid;
        if (i < n) {
            int p = g_ptr[i] + base_sh;
            g_ptr[i] = p;
            g_cur[i] = p;
        }
        if (i == 0) g_ptr[n] = E;
    }
    grid_barrier(BUILD_BLOCKS);

    int total = E + n * 16;
    int stride = BUILD_BLOCKS * 1024;
    for (int i = bid * 1024 + tid; i < total; i += stride) {
        if (i < E) {
            int c = g_colv[i];
            int pos = atomicAdd(&g_cur[c], 1);
            g_srcv[pos] = g_rowv[i];
        } else {
            int j = i - E;
            int node = j >> 4;
            float4 v = ((const float4*)x)[j];
            float d = g_dis[node];
            ((__half2*)g_hA)[j * 2 + 0] = __floats2half2_rn(v.x * d, v.y * d);
            ((__half2*)g_hA)[j * 2 + 1] = __floats2half2_rn(v.z * d, v.w * d);
            ((__half2*)g_xa)[j * 2 + 0] = __floats2half2_rn(v.x * ALPHA, v.y * ALPHA);
            ((__half2*)g_xa)[j * 2 + 1] = __floats2half2_rn(v.z * ALPHA, v.w * ALPHA);
        }
    }
}

// ---- gather quad: 4 independent nodes per warp (8 lanes each, uint4 rows) --
// As16 row = 0.9*dis[node]*(hself + sum_src hs[src]) + alpha*x[node]
__device__ __forceinline__ void gather_quad(
    const uint4* __restrict__ H4, const uint4* __restrict__ XA4,
    __half* As16, int row0 /*row of group 0 within tile*/, int quadbase,
    int n, int lane)
{
    int group = lane >> 3;
    int gl = lane & 7;
    int node = quadbase + group;
    bool valid = node < n;
    int nd = valid ? node : 0;
    int beg = g_ptr[nd];
    int end = g_ptr[nd + 1];
    int deg = valid ? (end - beg) : 0;

    __half2 ax, ay, az, aw;
    {
        uint4 acc = valid ? H4[nd * 8 + gl] : make_uint4(0u, 0u, 0u, 0u);  // self
        ax = *(__half2*)&acc.x; ay = *(__half2*)&acc.y;
        az = *(__half2*)&acc.z; aw = *(__half2*)&acc.w;
    }
    int dmax = max(deg, __shfl_xor_sync(0xffffffffu, deg, 8));
    dmax = max(dmax, __shfl_xor_sync(0xffffffffu, dmax, 16));

    for (int jb = 0; jb < dmax; jb += 8) {
        int sv = (jb + gl < deg) ? g_srcv[beg + jb + gl] : -1;
#pragma unroll
        for (int q = 0; q < 8; q++) {
            if (jb + q >= dmax) break;                       // warp-uniform
            int src = __shfl_sync(0xffffffffu, sv, (lane & 24) + q);
            if (src >= 0) {
                uint4 v = H4[src * 8 + gl];
                ax = __hadd2(ax, *(__half2*)&v.x);
                ay = __hadd2(ay, *(__half2*)&v.y);
                az = __hadd2(az, *(__half2*)&v.z);
                aw = __hadd2(aw, *(__half2*)&v.w);
            }
        }
    }
    float d = valid ? g_dis[nd] : 0.f;
    __half2 d9 = __float2half2_rn((1.0f - ALPHA) * d);
    uint4 xa = valid ? XA4[nd * 8 + gl] : make_uint4(0u, 0u, 0u, 0u);
    __half2 o0 = __hfma2(d9, ax, *(__half2*)&xa.x);
    __half2 o1 = __hfma2(d9, ay, *(__half2*)&xa.y);
    __half2 o2 = __hfma2(d9, az, *(__half2*)&xa.z);
    __half2 o3 = __hfma2(d9, aw, *(__half2*)&xa.w);
    uint4 pk;
    pk.x = *(unsigned int*)&o0; pk.y = *(unsigned int*)&o1;
    pk.z = *(unsigned int*)&o2; pk.w = *(unsigned int*)&o3;
    ((uint4*)(As16 + (row0 + group) * LDA))[gl] = pk;
}

__device__ __forceinline__ void gather_tile(const uint4* __restrict__ H4,
                                            const uint4* __restrict__ XA4,
                                            __half* As16, int r0, int n,
                                            int wid, int lane) {
    // warp handles rows wid*8 .. wid*8+7 in two quad passes
    gather_quad(H4, XA4, As16, wid * 8 + 0, r0 + wid * 8 + 0, n, lane);
    gather_quad(H4, XA4, As16, wid * 8 + 4, r0 + wid * 8 + 4, n, lane);
}

// ---------------- shared wmma GEMM: Cs(64x64 fp32) = As16 @ Ws16 ------------
__device__ __forceinline__ void wmma_gemm(const __half* As16, const __half* Ws16,
                                          float* Cs, int wid) {
    int tm = wid >> 1;               // 0..3
    int tn0 = (wid & 1) * 2;         // 0 or 2
    wmma::fragment<wmma::accumulator, 16, 16, 16, float> c0, c1;
    wmma::fill_fragment(c0, 0.f);
    wmma::fill_fragment(c1, 0.f);
#pragma unroll
    for (int k = 0; k < 4; k++) {
        wmma::fragment<wmma::matrix_a, 16, 16, 16, __half, wmma::row_major> a;
        wmma::fragment<wmma::matrix_b, 16, 16, 16, __half, wmma::row_major> b0, b1;
        wmma::load_matrix_sync(a, As16 + tm * 16 * LDA + k * 16, LDA);
        wmma::load_matrix_sync(b0, Ws16 + k * 16 * LDA + tn0 * 16, LDA);
        wmma::load_matrix_sync(b1, Ws16 + k * 16 * LDA + (tn0 + 1) * 16, LDA);
        wmma::mma_sync(c0, a, b0, c0);
        wmma::mma_sync(c1, a, b1, c1);
    }
    __syncthreads();  // everyone done reading As16/Ws16; Cs overlays them
    wmma::store_matrix_sync(Cs + tm * 16 * LDC + tn0 * 16, c0, LDC, wmma::mem_row_major);
    wmma::store_matrix_sync(Cs + tm * 16 * LDC + (tn0 + 1) * 16, c1, LDC, wmma::mem_row_major);
}

// ============ fused layer: gather + mix -> HMMA -> relu*dis -> fp16 out =====
__global__ void __launch_bounds__(256) k_layer(
    const __half* __restrict__ hs, const __half* __restrict__ xa,
    const float* __restrict__ W, __half* __restrict__ Out, int n) {
    __shared__ __align__(16) unsigned char smem_raw[SMEM_BYTES];
    __half* As16 = (__half*)smem_raw;                    // [64][LDA]
    __half* Wp   = (__half*)(smem_raw + 64 * LDA * 2);   // [64][LDA]
    float*  Cs   = (float*)smem_raw;                     // overlay [64][LDC]
    int tid = threadIdx.x;
    int r0 = blockIdx.x * 64;

    for (int i = tid; i < 4096; i += 256) {
        int k = i >> 6, j = i & 63;
        Wp[k * LDA + j] = __float2half(W[i]);
    }
    gather_tile((const uint4*)hs, (const uint4*)xa, As16, r0, n, tid >> 5, tid & 31);
    __syncthreads();

    wmma_gemm(As16, Wp, Cs, tid >> 5);
    __syncthreads();

    // epilogue: relu * dis -> fp16
    int rr = tid >> 2, cb = tid & 3;
    int r = r0 + rr;
    if (r < n) {
        float sc = g_dis[r];
        const float* row = Cs + rr * LDC + cb * 16;
        __half2 h[8];
#pragma unroll
        for (int q = 0; q < 8; q++) {
            float v0 = fmaxf(row[q * 2 + 0], 0.f) * sc;
            float v1 = fmaxf(row[q * 2 + 1], 0.f) * sc;
            h[q] = __floats2half2_rn(v0, v1);
        }
        uint4* dst = (uint4*)(Out + r * 64) + cb * 2;
        uint4 p0, p1;
        p0.x = *(unsigned int*)&h[0]; p0.y = *(unsigned int*)&h[1];
        p0.z = *(unsigned int*)&h[2]; p0.w = *(unsigned int*)&h[3];
        p1.x = *(unsigned int*)&h[4]; p1.y = *(unsigned int*)&h[5];
        p1.z = *(unsigned int*)&h[6]; p1.w = *(unsigned int*)&h[7];
        dst[0] = p0;
        dst[1] = p1;
    }
}

// ===== last layer: gather+mix -> HMMA -> relu -> GEMM64x16 * dis -> T16 =====
__global__ void __launch_bounds__(256) k_layer_last(
    const __half* __restrict__ hs, const __half* __restrict__ xa,
    const float* __restrict__ W, const float* __restrict__ W1,
    float* __restrict__ T16, int n) {
    __shared__ __align__(16) unsigned char smem_raw[SMEM_BYTES];
    __shared__ float W1s[64 * 16];
    __half* As16 = (__half*)smem_raw;
    __half* Wp   = (__half*)(smem_raw + 64 * LDA * 2);
    float*  Cs   = (float*)smem_raw;
    int tid = threadIdx.x;
    int r0 = blockIdx.x * 64;

    for (int i = tid; i < 4096; i += 256) {
        int k = i >> 6, j = i & 63;
        Wp[k * LDA + j] = __float2half(W[i]);
    }
    for (int i = tid; i < 1024; i += 256) W1s[i] = W1[i];
    gather_tile((const uint4*)hs, (const uint4*)xa, As16, r0, n, tid >> 5, tid & 31);
    __syncthreads();

    wmma_gemm(As16, Wp, Cs, tid >> 5);
    __syncthreads();

    // relu in place
    for (int i = tid; i < 4096; i += 256) {
        int rr = i >> 6, k = i & 63;
        Cs[rr * LDC + k] = fmaxf(Cs[rr * LDC + k], 0.f);
    }
    __syncthreads();

    // h(64x64 Cs) @ W1(64x16) -> T16, prescaled by dis
    for (int idx = tid; idx < 1024; idx += 256) {
        int rr = idx >> 4, j = idx & 15;
        int r = r0 + rr;
        if (r < n) {
            float a = 0.f;
#pragma unroll 8
            for (int k = 0; k < 64; k++) a += Cs[rr * LDC + k] * W1s[k * 16 + j];
            T16[r * 16 + j] = a * g_dis[r];
        }
    }
}

// ---------------- propagate 16-wide + b1, fused 16->1 GEMV, prescale ----------
__global__ void k_prop16_gemv(const float* __restrict__ ts, const float* __restrict__ b1,
                              const float* __restrict__ w2, float* __restrict__ ys, int n) {
    int t = threadIdx.x;
    int node = blockIdx.x * 16 + (t >> 4);
    int f = t & 15;
    bool ok = node < n;
    int beg = 0, end = 0;
    if (ok) { beg = g_ptr[node]; end = g_ptr[node + 1]; }
    float s = 0.f;
    int e = beg;
    for (; e + 4 <= end; e += 4) {
        int s0 = g_srcv[e], s1 = g_srcv[e + 1], s2 = g_srcv[e + 2], s3 = g_srcv[e + 3];
        s += ts[s0 * 16 + f] + ts[s1 * 16 + f] + ts[s2 * 16 + f] + ts[s3 * 16 + f];
    }
    for (; e < end; e++) s += ts[g_srcv[e] * 16 + f];
    float d = ok ? g_dis[node] : 0.f;
    float self = ok ? ts[node * 16 + f] : 0.f;
    float val = d * (s + self) + b1[f];
    float prod = val * w2[f];
    prod += __shfl_xor_sync(0xffffffffu, prod, 8);
    prod += __shfl_xor_sync(0xffffffffu, prod, 4);
    prod += __shfl_xor_sync(0xffffffffu, prod, 2);
    prod += __shfl_xor_sync(0xffffffffu, prod, 1);
    if (ok && f == 0) ys[node] = d * prod;
}

// ---------------- scalar propagate + b2 + sigmoid ----------------
__global__ void k_prop1_sig(const float* __restrict__ ys, const float* __restrict__ b2,
                            float* __restrict__ out, int n) {
    int node = blockIdx.x * blockDim.x + threadIdx.x;
    if (node >= n) return;
    int beg = g_ptr[node], end = g_ptr[node + 1];
    float s = 0.f;
    int e = beg;
    for (; e + 4 <= end; e += 4) {
        int s0 = g_srcv[e], s1 = g_srcv[e + 1], s2 = g_srcv[e + 2], s3 = g_srcv[e + 3];
        s += ys[s0] + ys[s1] + ys[s2] + ys[s3];
    }
    for (; e < end; e++) s += ys[g_srcv[e]];
    float d = g_dis[node];
    float v = d * (s + ys[node]) + b2[0];
    out[node] = 1.0f / (1.0f + expf(-v));
}

// ---------------- launch ----------------
extern "C" void kernel_launch(void* const* d_in, const int* in_sizes, int n_in,
                              void* d_out, int out_size) {
    const float* x  = (const float*)d_in[0];
    const void*  ei = d_in[1];
    const float* gw = (const float*)d_in[2];  // (4,64,64)
    const float* w1 = (const float*)d_in[3];  // (64,16)
    const float* b1 = (const float*)d_in[4];
    const float* w2 = (const float*)d_in[5];  // (16,1)
    const float* b2 = (const float*)d_in[6];
    float* out = (float*)d_out;

    const int N = in_sizes[0] / F;
    const int E = in_sizes[1] / 2;

    __half* hA; cudaGetSymbolAddress((void**)&hA, g_hA);
    __half* hB; cudaGetSymbolAddress((void**)&hB, g_hB);
    __half* xa; cudaGetSymbolAddress((void**)&xa, g_xa);
    float* t16; cudaGetSymbolAddress((void**)&t16, g_t16);
    float* yv;  cudaGetSymbolAddress((void**)&yv,  g_y);

    const int T = 256;
    int nb_n = (N + T - 1) / T;
    int nb_e = (E + T - 1) / T;
    int nb_g = (N + 63) / 64;
    int nb_g16 = (N + 15) / 16;

    // 0..2: graph norm + CSR build (+ fp16 prescales: hA = dis*x, xa = alpha*x)
    k_init<<<nb_n, T>>>((const int*)ei, N);
    k_convert_count<<<nb_e, T>>>(ei, E);
    k_build<<<BUILD_BLOCKS, 1024>>>(x, E, N);

    // 3..6: GCN2Conv stack: fused gather + HMMA per layer
    k_layer<<<nb_g, 256>>>(hA, xa, gw + 0 * 4096, hB, N);
    k_layer<<<nb_g, 256>>>(hB, xa, gw + 1 * 4096, hA, N);
    k_layer<<<nb_g, 256>>>(hA, xa, gw + 2 * 4096, hB, N);
    k_layer_last<<<nb_g, 256>>>(hB, xa, gw + 3 * 4096, w1, t16, N);

    // tail
    k_prop16_gemv<<<nb_g16, 256>>>(t16, b1, w2, yv, N);
    k_prop1_sig<<<nb_n, T>>>(yv, b2, out, N);
}